// round 1
// baseline (speedup 1.0000x reference)
#include <cuda_runtime.h>
#include <cstdint>

// ---------------- problem constants ----------------
#define NLAYERS 4
#define INSZ    80
#define DMODEL  512
#define NHEAD   8
#define DH      64
#define DFF     2048
#define BATCH   16
#define SMAX    512
#define NTOK    (BATCH * SMAX)   // 8192

// ---------------- scratch (device globals; no allocs allowed) ----------------
__device__ float g_h  [NTOK * DMODEL];       // hidden state
__device__ float g_qkv[NTOK * 3 * DMODEL];   // qkv projections
__device__ float g_ctx[NTOK * DMODEL];       // attention context
__device__ float g_ff [NTOK * DFF];          // ff intermediate

// ---------------- SGEMM: C[M,N] = A[M,K] * B[N,K]^T + bias (+epilogue) -------
// Tiles: 128x128x16, 256 threads, 8x8 per-thread microtile.
// Requires M%128==0, N%128==0, K%16==0 (all shapes here satisfy this).
enum { EPI_NONE = 0, EPI_PE = 1, EPI_RELU = 2, EPI_RES = 3 };

template <int EPI>
__global__ __launch_bounds__(256) void sgemm_kernel(
    const float* __restrict__ A, const float* __restrict__ B,
    const float* __restrict__ bias, const float* __restrict__ res,
    float* __restrict__ C, int M, int N, int K)
{
    __shared__ float As[16][132];
    __shared__ float Bs[16][132];

    const int tid = threadIdx.x;
    const int bm = blockIdx.y * 128;
    const int bn = blockIdx.x * 128;

    const int lr = tid >> 2;         // 0..63
    const int lc = (tid & 3) * 4;    // 0,4,8,12

    const int ty = tid >> 4;         // 0..15
    const int tx = tid & 15;         // 0..15

    float acc[8][8];
#pragma unroll
    for (int i = 0; i < 8; i++)
#pragma unroll
        for (int j = 0; j < 8; j++) acc[i][j] = 0.0f;

    for (int k0 = 0; k0 < K; k0 += 16) {
#pragma unroll
        for (int p = 0; p < 2; p++) {
            const int row = lr + p * 64;
            float4 a = *(const float4*)(A + (size_t)(bm + row) * K + k0 + lc);
            float4 b = *(const float4*)(B + (size_t)(bn + row) * K + k0 + lc);
            As[lc + 0][row] = a.x; As[lc + 1][row] = a.y;
            As[lc + 2][row] = a.z; As[lc + 3][row] = a.w;
            Bs[lc + 0][row] = b.x; Bs[lc + 1][row] = b.y;
            Bs[lc + 2][row] = b.z; Bs[lc + 3][row] = b.w;
        }
        __syncthreads();
#pragma unroll
        for (int kk = 0; kk < 16; kk++) {
            float a[8], b[8];
            *(float4*)(a)     = *(const float4*)&As[kk][ty * 8];
            *(float4*)(a + 4) = *(const float4*)&As[kk][ty * 8 + 4];
            *(float4*)(b)     = *(const float4*)&Bs[kk][tx * 8];
            *(float4*)(b + 4) = *(const float4*)&Bs[kk][tx * 8 + 4];
#pragma unroll
            for (int i = 0; i < 8; i++)
#pragma unroll
                for (int j = 0; j < 8; j++)
                    acc[i][j] += a[i] * b[j];
        }
        __syncthreads();
    }

    const int m0 = bm + ty * 8;
    const int n0 = bn + tx * 8;
    float bv[8];
#pragma unroll
    for (int j = 0; j < 8; j++) bv[j] = bias[n0 + j];

#pragma unroll
    for (int i = 0; i < 8; i++) {
        const int m = m0 + i;
        const int s = m & (SMAX - 1);   // token position within sequence
#pragma unroll
        for (int j = 0; j < 8; j++) {
            const int n = n0 + j;
            float v = acc[i][j] + bv[j];
            if (EPI == EPI_RELU) v = fmaxf(v, 0.0f);
            if (EPI == EPI_RES)  v += res[(size_t)m * N + n];
            if (EPI == EPI_PE) {
                const int de = n & ~1;
                float ang = (float)s * expf((float)de * (-9.210340371976184f / 512.0f));
                v += (n & 1) ? cosf(ang) : sinf(ang);
            }
            C[(size_t)m * N + n] = v;
        }
    }
}

// ---------------- fused attention -------------------------------------------
// Block: (qtile, head, batch). 32 queries x 512 keys, dh = 64, non-causal,
// key-padding mask (k >= len -> -1e9 before softmax, matching reference).
#define AQ   32
#define SPAD 516
#define KPAD 68
#define ATTN_SMEM ((AQ * SPAD + AQ * KPAD + 64 * KPAD) * 4)

__global__ __launch_bounds__(256) void attn_kernel(
    const float* __restrict__ qkv, const int* __restrict__ lens,
    float* __restrict__ ctx)
{
    extern __shared__ float smem[];
    float* sS = smem;                 // [AQ][SPAD] scores
    float* sQ = sS + AQ * SPAD;       // [AQ][KPAD] Q tile
    float* sKV = sQ + AQ * KPAD;      // [64][KPAD] K(transposed) / V tile

    const int qt = blockIdx.x;        // 0..15
    const int hd = blockIdx.y;        // 0..7
    const int b  = blockIdx.z;        // 0..15
    const int t  = threadIdx.x;
    const int len = lens[b];

    const float* base = qkv + (size_t)b * SMAX * (3 * DMODEL);

    // load Q tile [32 x 64] (padded rows for bank-conflict relief)
    {
        const int r = t >> 4;
        const int c = (t & 15) * 4;
#pragma unroll
        for (int p = 0; p < 2; p++) {
            const int q = r + p * 16;
            float4 v = *(const float4*)(base + (size_t)(qt * AQ + q) * (3 * DMODEL) + hd * DH + c);
            *(float4*)(sQ + q * KPAD + c) = v;
        }
    }

    const int wq = (t >> 5) * 4;      // 4 query rows per warp
    const int lk = t & 31;            // lane

    // ---- scores ----
    for (int kt = 0; kt < 8; kt++) {
        __syncthreads();
        // load K tile transposed: sKV[d][key]
        {
            const int r = t >> 4;
            const int c = (t & 15) * 4;
#pragma unroll
            for (int p = 0; p < 4; p++) {
                const int key = r + p * 16;
                float4 v = *(const float4*)(base + (size_t)(kt * 64 + key) * (3 * DMODEL)
                                            + DMODEL + hd * DH + c);
                sKV[(c + 0) * KPAD + key] = v.x;
                sKV[(c + 1) * KPAD + key] = v.y;
                sKV[(c + 2) * KPAD + key] = v.z;
                sKV[(c + 3) * KPAD + key] = v.w;
            }
        }
        __syncthreads();

        float acc[4][2] = {{0.f,0.f},{0.f,0.f},{0.f,0.f},{0.f,0.f}};
#pragma unroll 8
        for (int d = 0; d < 64; d++) {
            const float k0v = sKV[d * KPAD + lk * 2];
            const float k1v = sKV[d * KPAD + lk * 2 + 1];
#pragma unroll
            for (int i = 0; i < 4; i++) {
                const float qv = sQ[(wq + i) * KPAD + d];
                acc[i][0] += qv * k0v;
                acc[i][1] += qv * k1v;
            }
        }
#pragma unroll
        for (int i = 0; i < 4; i++)
#pragma unroll
            for (int j = 0; j < 2; j++) {
                const int kk = kt * 64 + lk * 2 + j;
                sS[(wq + i) * SPAD + kk] = (kk < len) ? acc[i][j] * 0.125f : -1e9f;
            }
    }
    __syncthreads();

    // ---- softmax: warp w owns rows w*4 .. w*4+3 ----
    {
        const int w = t >> 5, lane = t & 31;
        for (int qi = w * 4; qi < w * 4 + 4; qi++) {
            float* row = sS + qi * SPAD;
            float m = -1e30f;
            for (int k = lane; k < SMAX; k += 32) m = fmaxf(m, row[k]);
#pragma unroll
            for (int o = 16; o; o >>= 1) m = fmaxf(m, __shfl_xor_sync(0xffffffffu, m, o));
            float sum = 0.0f;
            for (int k = lane; k < SMAX; k += 32) {
                float e = expf(row[k] - m);
                row[k] = e;
                sum += e;
            }
#pragma unroll
            for (int o = 16; o; o >>= 1) sum += __shfl_xor_sync(0xffffffffu, sum, o);
            const float inv = 1.0f / sum;
            for (int k = lane; k < SMAX; k += 32) row[k] *= inv;
        }
    }

    // ---- P @ V ----
    float o[4][2] = {{0.f,0.f},{0.f,0.f},{0.f,0.f},{0.f,0.f}};
    const int dv = lk * 2;
    for (int kt = 0; kt < 8; kt++) {
        __syncthreads();
        // load V tile natural layout: sKV[key][d]
        {
            const int r = t >> 4;
            const int c = (t & 15) * 4;
#pragma unroll
            for (int p = 0; p < 4; p++) {
                const int key = r + p * 16;
                float4 v = *(const float4*)(base + (size_t)(kt * 64 + key) * (3 * DMODEL)
                                            + 2 * DMODEL + hd * DH + c);
                *(float4*)(sKV + key * KPAD + c) = v;
            }
        }
        __syncthreads();
#pragma unroll 8
        for (int k = 0; k < 64; k++) {
            const float v0 = sKV[k * KPAD + dv];
            const float v1 = sKV[k * KPAD + dv + 1];
#pragma unroll
            for (int i = 0; i < 4; i++) {
                const float p = sS[(wq + i) * SPAD + kt * 64 + k];
                o[i][0] += p * v0;
                o[i][1] += p * v1;
            }
        }
    }
#pragma unroll
    for (int i = 0; i < 4; i++) {
        const int q = qt * AQ + wq + i;
        float* cp = ctx + ((size_t)b * SMAX + q) * DMODEL + hd * DH + dv;
        cp[0] = o[i][0];
        cp[1] = o[i][1];
    }
}

// ---------------- LayerNorm (in place, per token row of 512) ----------------
__global__ __launch_bounds__(128) void ln_kernel(
    float* __restrict__ h, const float* __restrict__ g, const float* __restrict__ bta)
{
    __shared__ float red[8];
    const int row = blockIdx.x;
    const int t = threadIdx.x;
    float* p = h + (size_t)row * DMODEL + t * 4;
    float4 v = *(float4*)p;
    float s  = v.x + v.y + v.z + v.w;
    float ss = v.x * v.x + v.y * v.y + v.z * v.z + v.w * v.w;
#pragma unroll
    for (int o = 16; o; o >>= 1) {
        s  += __shfl_xor_sync(0xffffffffu, s, o);
        ss += __shfl_xor_sync(0xffffffffu, ss, o);
    }
    const int w = t >> 5;
    if ((t & 31) == 0) { red[w] = s; red[4 + w] = ss; }
    __syncthreads();
    s  = red[0] + red[1] + red[2] + red[3];
    ss = red[4] + red[5] + red[6] + red[7];
    const float mean = s * (1.0f / DMODEL);
    const float var  = ss * (1.0f / DMODEL) - mean * mean;
    const float rstd = rsqrtf(var + 1e-5f);
    float4 gg = *(const float4*)(g + t * 4);
    float4 bb = *(const float4*)(bta + t * 4);
    v.x = (v.x - mean) * rstd * gg.x + bb.x;
    v.y = (v.y - mean) * rstd * gg.y + bb.y;
    v.z = (v.z - mean) * rstd * gg.z + bb.z;
    v.w = (v.w - mean) * rstd * gg.w + bb.w;
    *(float4*)p = v;
}

// ---------------- masked mean pooling + lens output --------------------------
__global__ __launch_bounds__(DMODEL) void pool_kernel(
    const float* __restrict__ h, const int* __restrict__ lens,
    float* __restrict__ out, int out_size)
{
    const int b = blockIdx.x;
    const int d = threadIdx.x;
    const int len = lens[b];
    float s = 0.0f;
    for (int t = 0; t < len; t++)
        s += h[((size_t)b * SMAX + t) * DMODEL + d];
    out[b * DMODEL + d] = s / (float)len;
    if (d == 0 && out_size >= BATCH * DMODEL + BATCH)
        out[BATCH * DMODEL + b] = (float)len;
}

// ---------------- launch ------------------------------------------------------
extern "C" void kernel_launch(void* const* d_in, const int* in_sizes, int n_in,
                              void* d_out, int out_size)
{
    (void)in_sizes; (void)n_in;
    const float* x     = (const float*)d_in[0];
    const int*   lens  = (const int*)  d_in[1];
    const float* We    = (const float*)d_in[2];
    const float* be    = (const float*)d_in[3];
    const float* Wqkv  = (const float*)d_in[4];
    const float* bqkv  = (const float*)d_in[5];
    const float* Wo    = (const float*)d_in[6];
    const float* bo    = (const float*)d_in[7];
    const float* ln1g  = (const float*)d_in[8];
    const float* ln1b  = (const float*)d_in[9];
    const float* W1    = (const float*)d_in[10];
    const float* b1    = (const float*)d_in[11];
    const float* W2    = (const float*)d_in[12];
    const float* b2    = (const float*)d_in[13];
    const float* ln2g  = (const float*)d_in[14];
    const float* ln2b  = (const float*)d_in[15];
    float* out = (float*)d_out;

    void *ph, *pqkv, *pctx, *pff;
    cudaGetSymbolAddress(&ph,   g_h);
    cudaGetSymbolAddress(&pqkv, g_qkv);
    cudaGetSymbolAddress(&pctx, g_ctx);
    cudaGetSymbolAddress(&pff,  g_ff);
    float* h   = (float*)ph;
    float* qkv = (float*)pqkv;
    float* ctx = (float*)pctx;
    float* ff  = (float*)pff;

    cudaFuncSetAttribute(attn_kernel,
                         cudaFuncAttributeMaxDynamicSharedMemorySize, ATTN_SMEM);

    // embedding + positional encoding: h = x @ We^T + be + PE
    sgemm_kernel<EPI_PE><<<dim3(DMODEL / 128, NTOK / 128), 256>>>(
        x, We, be, nullptr, h, NTOK, DMODEL, INSZ);

    for (int l = 0; l < NLAYERS; l++) {
        const float* wq  = Wqkv + (size_t)l * 3 * DMODEL * DMODEL;
        const float* bq  = bqkv + (size_t)l * 3 * DMODEL;
        const float* wo  = Wo   + (size_t)l * DMODEL * DMODEL;
        const float* bO  = bo   + (size_t)l * DMODEL;
        const float* w1  = W1   + (size_t)l * DFF * DMODEL;
        const float* bf1 = b1   + (size_t)l * DFF;
        const float* w2  = W2   + (size_t)l * DMODEL * DFF;
        const float* bf2 = b2   + (size_t)l * DMODEL;

        // qkv = h @ Wqkv^T + bqkv
        sgemm_kernel<EPI_NONE><<<dim3(3 * DMODEL / 128, NTOK / 128), 256>>>(
            h, wq, bq, nullptr, qkv, NTOK, 3 * DMODEL, DMODEL);

        // attention -> ctx
        attn_kernel<<<dim3(SMAX / AQ, NHEAD, BATCH), 256, ATTN_SMEM>>>(qkv, lens, ctx);

        // h = h + ctx @ Wo^T + bo   (in place, element-local residual)
        sgemm_kernel<EPI_RES><<<dim3(DMODEL / 128, NTOK / 128), 256>>>(
            ctx, wo, bO, h, h, NTOK, DMODEL, DMODEL);
        // h = LN1(h)
        ln_kernel<<<NTOK, 128>>>(h, ln1g + l * DMODEL, ln1b + l * DMODEL);

        // ff = relu(h @ W1^T + b1)
        sgemm_kernel<EPI_RELU><<<dim3(DFF / 128, NTOK / 128), 256>>>(
            h, w1, bf1, nullptr, ff, NTOK, DFF, DMODEL);
        // h = h + ff @ W2^T + b2
        sgemm_kernel<EPI_RES><<<dim3(DMODEL / 128, NTOK / 128), 256>>>(
            ff, w2, bf2, h, h, NTOK, DMODEL, DFF);
        // h = LN2(h)
        ln_kernel<<<NTOK, 128>>>(h, ln2g + l * DMODEL, ln2b + l * DMODEL);
    }

    pool_kernel<<<BATCH, DMODEL>>>(h, lens, out, out_size);
}

// round 2
// speedup vs baseline: 1.6476x; 1.6476x over previous
#include <cuda_runtime.h>
#include <cuda_bf16.h>
#include <cstdint>

// ---------------- problem constants ----------------
#define NLAYERS 4
#define INSZ    80
#define DMODEL  512
#define NHEAD   8
#define DH      64
#define DFF     2048
#define BATCH   16
#define SMAX    512
#define NTOK    (BATCH * SMAX)   // 8192

// ---------------- scratch (device globals; no allocs allowed) ----------------
__device__ float g_h  [NTOK * DMODEL];       // hidden state
__device__ float g_qkv[NTOK * 3 * DMODEL];   // qkv projections
__device__ float g_ctx[NTOK * DMODEL];       // attention context
__device__ float g_ff [NTOK * DFF];          // ff intermediate

enum { EPI_NONE = 0, EPI_PE = 1, EPI_RELU = 2, EPI_RES = 3 };

// =============================================================================
// bf16 split-precision tensor-core GEMM:
//   C[M,N] = A[M,K] * B[N,K]^T + bias (+epilogue)
// A,B fp32 in gmem; split A = Ah + Al (bf16), B = Bh + Bl (bf16);
// acc += Ah*Bh + Ah*Bl + Al*Bh  (fp32 accum)  -> ~17 mantissa bits.
// Tiles 128x128x32, 256 threads, warp tile 64x32 (m16n8k16 HMMA).
// Requires M%128==0, N%128==0, K%32==0.
// =============================================================================
#define BK    32
#define LDS40 40                 // padded k-stride (bank-conflict-free frag loads)
#define PLANE (128 * LDS40)      // bf16 elems per [128][40] plane
#define GSMEM (4 * 2 * PLANE * 2) // Ah,Al,Bh,Bl x 2 buffers x bf16  = 81920 B

__device__ __forceinline__ void mma16816(float* d, const uint32_t* a, const uint32_t* b) {
    asm volatile(
        "mma.sync.aligned.m16n8k16.row.col.f32.bf16.bf16.f32 "
        "{%0,%1,%2,%3},{%4,%5,%6,%7},{%8,%9},{%0,%1,%2,%3};\n"
        : "+f"(d[0]), "+f"(d[1]), "+f"(d[2]), "+f"(d[3])
        : "r"(a[0]), "r"(a[1]), "r"(a[2]), "r"(a[3]), "r"(b[0]), "r"(b[1]));
}

__device__ __forceinline__ uint32_t ld32(const __nv_bfloat16* p) {
    return *reinterpret_cast<const uint32_t*>(p);
}

__device__ __forceinline__ void cvt_store4(__nv_bfloat16* dh, __nv_bfloat16* dl, float4 v) {
    union { __nv_bfloat16 b[4]; uint2 u; } H, L;
    H.b[0] = __float2bfloat16(v.x); L.b[0] = __float2bfloat16(v.x - __bfloat162float(H.b[0]));
    H.b[1] = __float2bfloat16(v.y); L.b[1] = __float2bfloat16(v.y - __bfloat162float(H.b[1]));
    H.b[2] = __float2bfloat16(v.z); L.b[2] = __float2bfloat16(v.z - __bfloat162float(H.b[2]));
    H.b[3] = __float2bfloat16(v.w); L.b[3] = __float2bfloat16(v.w - __bfloat162float(H.b[3]));
    *reinterpret_cast<uint2*>(dh) = H.u;
    *reinterpret_cast<uint2*>(dl) = L.u;
}

template <int EPI>
__global__ __launch_bounds__(256) void bgemm_kernel(
    const float* __restrict__ A, const float* __restrict__ B,
    const float* __restrict__ bias, const float* __restrict__ res,
    float* __restrict__ C, int M, int N, int K)
{
    extern __shared__ __nv_bfloat16 sm[];
    __nv_bfloat16* sAh = sm;
    __nv_bfloat16* sAl = sm + 2 * PLANE;
    __nv_bfloat16* sBh = sm + 4 * PLANE;
    __nv_bfloat16* sBl = sm + 6 * PLANE;

    const int tid = threadIdx.x;
    const int bm = blockIdx.y * 128;
    const int bn = blockIdx.x * 128;

    const int wid  = tid >> 5;
    const int wm   = wid & 1;       // 0..1 -> 64-row half
    const int wn   = wid >> 1;      // 0..3 -> 32-col quarter
    const int lane = tid & 31;
    const int g    = lane >> 2;     // group row 0..7
    const int tg   = lane & 3;      // thread-in-group

    // gmem staging mapping: 4 float4 per thread per matrix per K-tile
    const int srow = tid >> 3;            // base row step 32 per p? no: idx math below
    (void)srow;

    float acc[4][4][4];
#pragma unroll
    for (int i = 0; i < 4; i++)
#pragma unroll
        for (int j = 0; j < 4; j++)
#pragma unroll
            for (int r = 0; r < 4; r++) acc[i][j][r] = 0.0f;

    const int ntile = K / BK;

    // ---- prologue: load tile 0 ----
    {
#pragma unroll
        for (int p = 0; p < 4; p++) {
            const int idx = tid + p * 256;
            const int row = idx >> 3;
            const int c4  = (idx & 7) * 4;
            float4 va = *(const float4*)(A + (size_t)(bm + row) * K + c4);
            float4 vb = *(const float4*)(B + (size_t)(bn + row) * K + c4);
            cvt_store4(sAh + row * LDS40 + c4, sAl + row * LDS40 + c4, va);
            cvt_store4(sBh + row * LDS40 + c4, sBl + row * LDS40 + c4, vb);
        }
    }
    __syncthreads();

    for (int t = 0; t < ntile; t++) {
        const int cur = (t & 1) * PLANE;
        const int nxt = ((t + 1) & 1) * PLANE;

        // prefetch next K-tile into registers
        float4 ra[4], rb[4];
        const bool have_next = (t + 1 < ntile);
        if (have_next) {
            const int k0 = (t + 1) * BK;
#pragma unroll
            for (int p = 0; p < 4; p++) {
                const int idx = tid + p * 256;
                const int row = idx >> 3;
                const int c4  = (idx & 7) * 4;
                ra[p] = *(const float4*)(A + (size_t)(bm + row) * K + k0 + c4);
                rb[p] = *(const float4*)(B + (size_t)(bn + row) * K + k0 + c4);
            }
        }

        // ---- compute on current buffer ----
#pragma unroll
        for (int ks = 0; ks < 2; ks++) {
            const int kc = ks * 16 + 2 * tg;
            uint32_t ah[4][4], al[4][4], bh[4][2], bl[4][2];
#pragma unroll
            for (int mi = 0; mi < 4; mi++) {
                const int r = wm * 64 + mi * 16 + g;
                const __nv_bfloat16* pH = sAh + cur + r * LDS40 + kc;
                const __nv_bfloat16* pL = sAl + cur + r * LDS40 + kc;
                ah[mi][0] = ld32(pH);
                ah[mi][1] = ld32(pH + 8 * LDS40);
                ah[mi][2] = ld32(pH + 8);
                ah[mi][3] = ld32(pH + 8 * LDS40 + 8);
                al[mi][0] = ld32(pL);
                al[mi][1] = ld32(pL + 8 * LDS40);
                al[mi][2] = ld32(pL + 8);
                al[mi][3] = ld32(pL + 8 * LDS40 + 8);
            }
#pragma unroll
            for (int ni = 0; ni < 4; ni++) {
                const int r = wn * 32 + ni * 8 + g;
                const __nv_bfloat16* pH = sBh + cur + r * LDS40 + kc;
                const __nv_bfloat16* pL = sBl + cur + r * LDS40 + kc;
                bh[ni][0] = ld32(pH);
                bh[ni][1] = ld32(pH + 8);
                bl[ni][0] = ld32(pL);
                bl[ni][1] = ld32(pL + 8);
            }
#pragma unroll
            for (int mi = 0; mi < 4; mi++)
#pragma unroll
                for (int ni = 0; ni < 4; ni++) {
                    mma16816(acc[mi][ni], ah[mi], bh[ni]);
                    mma16816(acc[mi][ni], ah[mi], bl[ni]);
                    mma16816(acc[mi][ni], al[mi], bh[ni]);
                }
        }

        // ---- store prefetched tile into the other buffer ----
        if (have_next) {
#pragma unroll
            for (int p = 0; p < 4; p++) {
                const int idx = tid + p * 256;
                const int row = idx >> 3;
                const int c4  = (idx & 7) * 4;
                cvt_store4(sAh + nxt + row * LDS40 + c4, sAl + nxt + row * LDS40 + c4, ra[p]);
                cvt_store4(sBh + nxt + row * LDS40 + c4, sBl + nxt + row * LDS40 + c4, rb[p]);
            }
        }
        __syncthreads();
    }

    // ---- epilogue ----
#pragma unroll
    for (int mi = 0; mi < 4; mi++) {
#pragma unroll
        for (int ni = 0; ni < 4; ni++) {
            const int m = bm + wm * 64 + mi * 16 + g;
            const int n = bn + wn * 32 + ni * 8 + tg * 2;
            const float b0 = bias[n], b1 = bias[n + 1];
#pragma unroll
            for (int h = 0; h < 2; h++) {
                const int mm = m + h * 8;
                float v0 = acc[mi][ni][h * 2 + 0] + b0;
                float v1 = acc[mi][ni][h * 2 + 1] + b1;
                if (EPI == EPI_RELU) { v0 = fmaxf(v0, 0.0f); v1 = fmaxf(v1, 0.0f); }
                if (EPI == EPI_RES) {
                    const float* rp = res + (size_t)mm * N + n;
                    v0 += rp[0]; v1 += rp[1];
                }
                float* cp = C + (size_t)mm * N + n;
                cp[0] = v0; cp[1] = v1;
            }
        }
    }
}

// ---------------- fp32 SGEMM (kept only for the tiny embed GEMM, K=80) -------
template <int EPI>
__global__ __launch_bounds__(256) void sgemm_kernel(
    const float* __restrict__ A, const float* __restrict__ B,
    const float* __restrict__ bias, const float* __restrict__ res,
    float* __restrict__ C, int M, int N, int K)
{
    __shared__ float As[16][132];
    __shared__ float Bs[16][132];

    const int tid = threadIdx.x;
    const int bm = blockIdx.y * 128;
    const int bn = blockIdx.x * 128;

    const int lr = tid >> 2;
    const int lc = (tid & 3) * 4;
    const int ty = tid >> 4;
    const int tx = tid & 15;

    float acc[8][8];
#pragma unroll
    for (int i = 0; i < 8; i++)
#pragma unroll
        for (int j = 0; j < 8; j++) acc[i][j] = 0.0f;

    for (int k0 = 0; k0 < K; k0 += 16) {
#pragma unroll
        for (int p = 0; p < 2; p++) {
            const int row = lr + p * 64;
            float4 a = *(const float4*)(A + (size_t)(bm + row) * K + k0 + lc);
            float4 b = *(const float4*)(B + (size_t)(bn + row) * K + k0 + lc);
            As[lc + 0][row] = a.x; As[lc + 1][row] = a.y;
            As[lc + 2][row] = a.z; As[lc + 3][row] = a.w;
            Bs[lc + 0][row] = b.x; Bs[lc + 1][row] = b.y;
            Bs[lc + 2][row] = b.z; Bs[lc + 3][row] = b.w;
        }
        __syncthreads();
#pragma unroll
        for (int kk = 0; kk < 16; kk++) {
            float a[8], b[8];
            *(float4*)(a)     = *(const float4*)&As[kk][ty * 8];
            *(float4*)(a + 4) = *(const float4*)&As[kk][ty * 8 + 4];
            *(float4*)(b)     = *(const float4*)&Bs[kk][tx * 8];
            *(float4*)(b + 4) = *(const float4*)&Bs[kk][tx * 8 + 4];
#pragma unroll
            for (int i = 0; i < 8; i++)
#pragma unroll
                for (int j = 0; j < 8; j++)
                    acc[i][j] += a[i] * b[j];
        }
        __syncthreads();
    }

    const int m0 = bm + ty * 8;
    const int n0 = bn + tx * 8;
    float bv[8];
#pragma unroll
    for (int j = 0; j < 8; j++) bv[j] = bias[n0 + j];

#pragma unroll
    for (int i = 0; i < 8; i++) {
        const int m = m0 + i;
        const int s = m & (SMAX - 1);
#pragma unroll
        for (int j = 0; j < 8; j++) {
            const int n = n0 + j;
            float v = acc[i][j] + bv[j];
            if (EPI == EPI_RELU) v = fmaxf(v, 0.0f);
            if (EPI == EPI_RES)  v += res[(size_t)m * N + n];
            if (EPI == EPI_PE) {
                const int de = n & ~1;
                float ang = (float)s * expf((float)de * (-9.210340371976184f / 512.0f));
                v += (n & 1) ? cosf(ang) : sinf(ang);
            }
            C[(size_t)m * N + n] = v;
        }
    }
}

// ---------------- fused attention (unchanged from R1) ------------------------
#define AQ   32
#define SPAD 516
#define KPAD 68
#define ATTN_SMEM ((AQ * SPAD + AQ * KPAD + 64 * KPAD) * 4)

__global__ __launch_bounds__(256) void attn_kernel(
    const float* __restrict__ qkv, const int* __restrict__ lens,
    float* __restrict__ ctx)
{
    extern __shared__ float smem[];
    float* sS = smem;
    float* sQ = sS + AQ * SPAD;
    float* sKV = sQ + AQ * KPAD;

    const int qt = blockIdx.x;
    const int hd = blockIdx.y;
    const int b  = blockIdx.z;
    const int t  = threadIdx.x;
    const int len = lens[b];

    const float* base = qkv + (size_t)b * SMAX * (3 * DMODEL);

    {
        const int r = t >> 4;
        const int c = (t & 15) * 4;
#pragma unroll
        for (int p = 0; p < 2; p++) {
            const int q = r + p * 16;
            float4 v = *(const float4*)(base + (size_t)(qt * AQ + q) * (3 * DMODEL) + hd * DH + c);
            *(float4*)(sQ + q * KPAD + c) = v;
        }
    }

    const int wq = (t >> 5) * 4;
    const int lk = t & 31;

    for (int kt = 0; kt < 8; kt++) {
        __syncthreads();
        {
            const int r = t >> 4;
            const int c = (t & 15) * 4;
#pragma unroll
            for (int p = 0; p < 4; p++) {
                const int key = r + p * 16;
                float4 v = *(const float4*)(base + (size_t)(kt * 64 + key) * (3 * DMODEL)
                                            + DMODEL + hd * DH + c);
                sKV[(c + 0) * KPAD + key] = v.x;
                sKV[(c + 1) * KPAD + key] = v.y;
                sKV[(c + 2) * KPAD + key] = v.z;
                sKV[(c + 3) * KPAD + key] = v.w;
            }
        }
        __syncthreads();

        float acc[4][2] = {{0.f,0.f},{0.f,0.f},{0.f,0.f},{0.f,0.f}};
#pragma unroll 8
        for (int d = 0; d < 64; d++) {
            const float k0v = sKV[d * KPAD + lk * 2];
            const float k1v = sKV[d * KPAD + lk * 2 + 1];
#pragma unroll
            for (int i = 0; i < 4; i++) {
                const float qv = sQ[(wq + i) * KPAD + d];
                acc[i][0] += qv * k0v;
                acc[i][1] += qv * k1v;
            }
        }
#pragma unroll
        for (int i = 0; i < 4; i++)
#pragma unroll
            for (int j = 0; j < 2; j++) {
                const int kk = kt * 64 + lk * 2 + j;
                sS[(wq + i) * SPAD + kk] = (kk < len) ? acc[i][j] * 0.125f : -1e9f;
            }
    }
    __syncthreads();

    {
        const int w = t >> 5, lane = t & 31;
        for (int qi = w * 4; qi < w * 4 + 4; qi++) {
            float* row = sS + qi * SPAD;
            float m = -1e30f;
            for (int k = lane; k < SMAX; k += 32) m = fmaxf(m, row[k]);
#pragma unroll
            for (int o = 16; o; o >>= 1) m = fmaxf(m, __shfl_xor_sync(0xffffffffu, m, o));
            float sum = 0.0f;
            for (int k = lane; k < SMAX; k += 32) {
                float e = expf(row[k] - m);
                row[k] = e;
                sum += e;
            }
#pragma unroll
            for (int o = 16; o; o >>= 1) sum += __shfl_xor_sync(0xffffffffu, sum, o);
            const float inv = 1.0f / sum;
            for (int k = lane; k < SMAX; k += 32) row[k] *= inv;
        }
    }

    float o[4][2] = {{0.f,0.f},{0.f,0.f},{0.f,0.f},{0.f,0.f}};
    const int dv = lk * 2;
    for (int kt = 0; kt < 8; kt++) {
        __syncthreads();
        {
            const int r = t >> 4;
            const int c = (t & 15) * 4;
#pragma unroll
            for (int p = 0; p < 4; p++) {
                const int key = r + p * 16;
                float4 v = *(const float4*)(base + (size_t)(kt * 64 + key) * (3 * DMODEL)
                                            + 2 * DMODEL + hd * DH + c);
                *(float4*)(sKV + key * KPAD + c) = v;
            }
        }
        __syncthreads();
#pragma unroll 8
        for (int k = 0; k < 64; k++) {
            const float v0 = sKV[k * KPAD + dv];
            const float v1 = sKV[k * KPAD + dv + 1];
#pragma unroll
            for (int i = 0; i < 4; i++) {
                const float p = sS[(wq + i) * SPAD + kt * 64 + k];
                o[i][0] += p * v0;
                o[i][1] += p * v1;
            }
        }
    }
#pragma unroll
    for (int i = 0; i < 4; i++) {
        const int q = qt * AQ + wq + i;
        float* cp = ctx + ((size_t)b * SMAX + q) * DMODEL + hd * DH + dv;
        cp[0] = o[i][0];
        cp[1] = o[i][1];
    }
}

// ---------------- LayerNorm (in place) ---------------------------------------
__global__ __launch_bounds__(128) void ln_kernel(
    float* __restrict__ h, const float* __restrict__ g, const float* __restrict__ bta)
{
    __shared__ float red[8];
    const int row = blockIdx.x;
    const int t = threadIdx.x;
    float* p = h + (size_t)row * DMODEL + t * 4;
    float4 v = *(float4*)p;
    float s  = v.x + v.y + v.z + v.w;
    float ss = v.x * v.x + v.y * v.y + v.z * v.z + v.w * v.w;
#pragma unroll
    for (int o = 16; o; o >>= 1) {
        s  += __shfl_xor_sync(0xffffffffu, s, o);
        ss += __shfl_xor_sync(0xffffffffu, ss, o);
    }
    const int w = t >> 5;
    if ((t & 31) == 0) { red[w] = s; red[4 + w] = ss; }
    __syncthreads();
    s  = red[0] + red[1] + red[2] + red[3];
    ss = red[4] + red[5] + red[6] + red[7];
    const float mean = s * (1.0f / DMODEL);
    const float var  = ss * (1.0f / DMODEL) - mean * mean;
    const float rstd = rsqrtf(var + 1e-5f);
    float4 gg = *(const float4*)(g + t * 4);
    float4 bb = *(const float4*)(bta + t * 4);
    v.x = (v.x - mean) * rstd * gg.x + bb.x;
    v.y = (v.y - mean) * rstd * gg.y + bb.y;
    v.z = (v.z - mean) * rstd * gg.z + bb.z;
    v.w = (v.w - mean) * rstd * gg.w + bb.w;
    *(float4*)p = v;
}

// ---------------- masked mean pooling + lens ---------------------------------
__global__ __launch_bounds__(DMODEL) void pool_kernel(
    const float* __restrict__ h, const int* __restrict__ lens,
    float* __restrict__ out, int out_size)
{
    const int b = blockIdx.x;
    const int d = threadIdx.x;
    const int len = lens[b];
    float s = 0.0f;
    for (int t = 0; t < len; t++)
        s += h[((size_t)b * SMAX + t) * DMODEL + d];
    out[b * DMODEL + d] = s / (float)len;
    if (d == 0 && out_size >= BATCH * DMODEL + BATCH)
        out[BATCH * DMODEL + b] = (float)len;
}

// ---------------- launch ------------------------------------------------------
extern "C" void kernel_launch(void* const* d_in, const int* in_sizes, int n_in,
                              void* d_out, int out_size)
{
    (void)in_sizes; (void)n_in;
    const float* x     = (const float*)d_in[0];
    const int*   lens  = (const int*)  d_in[1];
    const float* We    = (const float*)d_in[2];
    const float* be    = (const float*)d_in[3];
    const float* Wqkv  = (const float*)d_in[4];
    const float* bqkv  = (const float*)d_in[5];
    const float* Wo    = (const float*)d_in[6];
    const float* bo    = (const float*)d_in[7];
    const float* ln1g  = (const float*)d_in[8];
    const float* ln1b  = (const float*)d_in[9];
    const float* W1    = (const float*)d_in[10];
    const float* b1    = (const float*)d_in[11];
    const float* W2    = (const float*)d_in[12];
    const float* b2    = (const float*)d_in[13];
    const float* ln2g  = (const float*)d_in[14];
    const float* ln2b  = (const float*)d_in[15];
    float* out = (float*)d_out;

    void *ph, *pqkv, *pctx, *pff;
    cudaGetSymbolAddress(&ph,   g_h);
    cudaGetSymbolAddress(&pqkv, g_qkv);
    cudaGetSymbolAddress(&pctx, g_ctx);
    cudaGetSymbolAddress(&pff,  g_ff);
    float* h   = (float*)ph;
    float* qkv = (float*)pqkv;
    float* ctx = (float*)pctx;
    float* ff  = (float*)pff;

    cudaFuncSetAttribute(attn_kernel,
                         cudaFuncAttributeMaxDynamicSharedMemorySize, ATTN_SMEM);
    cudaFuncSetAttribute(bgemm_kernel<EPI_NONE>,
                         cudaFuncAttributeMaxDynamicSharedMemorySize, GSMEM);
    cudaFuncSetAttribute(bgemm_kernel<EPI_RELU>,
                         cudaFuncAttributeMaxDynamicSharedMemorySize, GSMEM);
    cudaFuncSetAttribute(bgemm_kernel<EPI_RES>,
                         cudaFuncAttributeMaxDynamicSharedMemorySize, GSMEM);

    // embedding + positional encoding (tiny, fp32 path): h = x @ We^T + be + PE
    sgemm_kernel<EPI_PE><<<dim3(DMODEL / 128, NTOK / 128), 256>>>(
        x, We, be, nullptr, h, NTOK, DMODEL, INSZ);

    for (int l = 0; l < NLAYERS; l++) {
        const float* wq  = Wqkv + (size_t)l * 3 * DMODEL * DMODEL;
        const float* bq  = bqkv + (size_t)l * 3 * DMODEL;
        const float* wo  = Wo   + (size_t)l * DMODEL * DMODEL;
        const float* bO  = bo   + (size_t)l * DMODEL;
        const float* w1  = W1   + (size_t)l * DFF * DMODEL;
        const float* bf1 = b1   + (size_t)l * DFF;
        const float* w2  = W2   + (size_t)l * DMODEL * DFF;
        const float* bf2 = b2   + (size_t)l * DMODEL;

        // qkv = h @ Wqkv^T + bqkv
        bgemm_kernel<EPI_NONE><<<dim3(3 * DMODEL / 128, NTOK / 128), 256, GSMEM>>>(
            h, wq, bq, nullptr, qkv, NTOK, 3 * DMODEL, DMODEL);

        // attention -> ctx
        attn_kernel<<<dim3(SMAX / AQ, NHEAD, BATCH), 256, ATTN_SMEM>>>(qkv, lens, ctx);

        // h = h + ctx @ Wo^T + bo
        bgemm_kernel<EPI_RES><<<dim3(DMODEL / 128, NTOK / 128), 256, GSMEM>>>(
            ctx, wo, bO, h, h, NTOK, DMODEL, DMODEL);
        ln_kernel<<<NTOK, 128>>>(h, ln1g + l * DMODEL, ln1b + l * DMODEL);

        // ff = relu(h @ W1^T + b1)
        bgemm_kernel<EPI_RELU><<<dim3(DFF / 128, NTOK / 128), 256, GSMEM>>>(
            h, w1, bf1, nullptr, ff, NTOK, DFF, DMODEL);
        // h = h + ff @ W2^T + b2
        bgemm_kernel<EPI_RES><<<dim3(DMODEL / 128, NTOK / 128), 256, GSMEM>>>(
            ff, w2, bf2, h, h, NTOK, DMODEL, DFF);
        ln_kernel<<<NTOK, 128>>>(h, ln2g + l * DMODEL, ln2b + l * DMODEL);
    }

    pool_kernel<<<BATCH, DMODEL>>>(h, lens, out, out_size);
}